// round 11
// baseline (speedup 1.0000x reference)
#include <cuda_runtime.h>

// TrigoLinear: out[b,o] = sum_i sin(x[b,i]*w_sin[o,i] + b_sin[o,i]) * w_out[o,i] + b_out[o]
// bb=8 oo=4 hybrid micro-kernel (R10, best) + intra-CTA k-split x4:
// 512 threads = 4 quarters, each runs 8 of 32 k-slices per tile -> 4 warps/SMSP.
// oo pair 0: packed arg-fma + scalar MUFU; oo pair 1: packed f32x2 degree-3 poly.

#define B_DIM   1024
#define IN_DIM  512
#define OUT_DIM 512

#define BM 64
#define BN 64
#define BK 32

// flat smem offsets (floats)
#define OX2  0            // dup x: [32][132]  (528B rows, 16B-aligned)
#define ROWX 132
#define OWS  4224         // w_sin: [32][68]
#define OBS  6400         // b_sin
#define OWO  8576         // w_out
#define ROWO 68
#define SMEM_FLOATS 12288  // 48 KB (combine area needs 3*4096)

typedef unsigned long long ull;

struct U2 { ull lo, hi; };
union F4U { float4 f; U2 u; };
union F2U { float2 f; ull u; };

__device__ __forceinline__ ull fma2_(ull a, ull b, ull c) {
    ull d; asm("fma.rn.f32x2 %0, %1, %2, %3;" : "=l"(d) : "l"(a), "l"(b), "l"(c)); return d;
}
__device__ __forceinline__ ull mul2_(ull a, ull b) {
    ull d; asm("mul.rn.f32x2 %0, %1, %2;" : "=l"(d) : "l"(a), "l"(b)); return d;
}
__device__ __forceinline__ float sin_mufu(float a) {
    float d; asm("sin.approx.f32 %0, %1;" : "=f"(d) : "f"(a)); return d;
}
__device__ __forceinline__ ull pkc(float c) {
    F2U t; t.f = make_float2(c, c); return t.u;
}

__global__ __launch_bounds__(512, 1)
void trigo_kernel(const float* __restrict__ x,
                  const float* __restrict__ weight,
                  const float* __restrict__ bias,
                  float* __restrict__ out) {
    __shared__ __align__(16) float S[SMEM_FLOATS];

    const int tid  = threadIdx.x;
    const int quar = tid >> 7;        // 0..3: which k-quarter of each tile
    const int tid2 = tid & 127;
    const int tx = tid2 & 15;         // o = tx*4
    const int ty = tid2 >> 4;         // b = ty*8 (ty 0..7)
    const int bRow = blockIdx.y * BM;
    const int oCol = blockIdx.x * BN;

    const float2* __restrict__ w2 = (const float2*)weight;

    // staging registers (software pipeline over LDG): 2048 elems / 512 thr = 4 each
    float  rx[4];
    float2 rw[4];
    float  rb[4];

    // ---- prologue: tile 0 ----
    #pragma unroll
    for (int j = 0; j < 4; j++) {
        int idx = tid + j * 512;
        int r = idx >> 5, k = idx & 31;
        rx[j] = x[(bRow + r) * IN_DIM + k];
        rw[j] = w2[(oCol + r) * IN_DIM + k];
        rb[j] = bias[(oCol + r) * (IN_DIM + 1) + k];
    }
    #pragma unroll
    for (int j = 0; j < 4; j++) {
        int idx = tid + j * 512;
        int r = idx >> 5, k = idx & 31;
        *(float2*)&S[OX2 + k * ROWX + r * 2] = make_float2(rx[j], rx[j]);
        S[OWO + k * ROWO + r] = rw[j].x;
        S[OWS + k * ROWO + r] = rw[j].y;
        S[OBS + k * ROWO + r] = rb[j];
    }
    __syncthreads();

    const ull C3  = pkc(-1.6666667e-1f);
    const ull ONE = pkc(1.0f);

    float accA0[8], accA1[8];   // MUFU path scalars (oo 0,1) per bb
    ull   accB[8];              // poly path packed (oo 2,3) per bb
    #pragma unroll
    for (int bb = 0; bb < 8; bb++) { accA0[bb] = 0.f; accA1[bb] = 0.f; accB[bb] = 0ull; }

    const int kOfs = quar * (BK / 4);   // this quarter's k-offset within each tile

    for (int k0 = 0; k0 < IN_DIM; k0 += BK) {
        if (k0 + BK < IN_DIM) {
            #pragma unroll
            for (int j = 0; j < 4; j++) {
                int idx = tid + j * 512;
                int r = idx >> 5, k = idx & 31;
                rx[j] = x[(bRow + r) * IN_DIM + k0 + BK + k];
                rw[j] = w2[(oCol + r) * IN_DIM + k0 + BK + k];
                rb[j] = bias[(oCol + r) * (IN_DIM + 1) + k0 + BK + k];
            }
        }

        #pragma unroll 2
        for (int kk = 0; kk < BK / 4; kk++) {
            const int k = kOfs + kk;
            F4U ws; ws.f = *(const float4*)&S[OWS + k * ROWO + tx * 4];
            F4U bs; bs.f = *(const float4*)&S[OBS + k * ROWO + tx * 4];
            F4U wo; wo.f = *(const float4*)&S[OWO + k * ROWO + tx * 4];
            F2U woA; woA.u = wo.u.lo;   // scalar view for MUFU path

            #pragma unroll
            for (int q = 0; q < 4; q++) {
                // one LDS.128 = {x0,x0,x1,x1}: two packed dup pairs
                F4U xq; xq.f = *(const float4*)&S[OX2 + k * ROWX + ty * 16 + q * 4];

                #pragma unroll
                for (int e = 0; e < 2; e++) {
                    const int bb = q * 2 + e;
                    const ull xd = e ? xq.u.hi : xq.u.lo;

                    // ---- MUFU path (oo 0,1): packed arg, scalar sin + acc ----
                    F2U t; t.u = fma2_(xd, ws.u.lo, bs.u.lo);
                    accA0[bb] = fmaf(sin_mufu(t.f.x), woA.f.x, accA0[bb]);
                    accA1[bb] = fmaf(sin_mufu(t.f.y), woA.f.y, accA1[bb]);

                    // ---- poly path (oo 2,3): acc += (t*wo)*(1 + c3*t^2) ----
                    ull tp = fma2_(xd, ws.u.hi, bs.u.hi);
                    ull sp = mul2_(tp, tp);
                    ull hp = fma2_(C3, sp, ONE);
                    ull up = mul2_(tp, wo.u.hi);
                    accB[bb] = fma2_(up, hp, accB[bb]);
                }
            }
        }

        __syncthreads();
        if (k0 + BK < IN_DIM) {
            #pragma unroll
            for (int j = 0; j < 4; j++) {
                int idx = tid + j * 512;
                int r = idx >> 5, k = idx & 31;
                *(float2*)&S[OX2 + k * ROWX + r * 2] = make_float2(rx[j], rx[j]);
                S[OWO + k * ROWO + r] = rw[j].x;
                S[OWS + k * ROWO + r] = rw[j].y;
                S[OBS + k * ROWO + r] = rb[j];
            }
            __syncthreads();
        }
    }

    // ---- combine the four k-quarters through smem ----
    __syncthreads();   // all compute done; safe to reuse S
    if (quar != 0) {
        float* dst = &S[(quar - 1) * 4096 + tid2 * 32];
        #pragma unroll
        for (int bb = 0; bb < 8; bb++) {
            float4 v;
            v.x = accA0[bb]; v.y = accA1[bb];
            F2U p; p.u = accB[bb];
            v.z = p.f.x; v.w = p.f.y;
            *(float4*)&dst[bb * 4] = v;
        }
    }
    __syncthreads();

    if (quar == 0) {
        float bo0 = bias[(oCol + tx * 4 + 0) * (IN_DIM + 1) + IN_DIM];
        float bo1 = bias[(oCol + tx * 4 + 1) * (IN_DIM + 1) + IN_DIM];
        float bo2 = bias[(oCol + tx * 4 + 2) * (IN_DIM + 1) + IN_DIM];
        float bo3 = bias[(oCol + tx * 4 + 3) * (IN_DIM + 1) + IN_DIM];

        #pragma unroll
        for (int bb = 0; bb < 8; bb++) {
            float4 p1 = *(const float4*)&S[0 * 4096 + tid2 * 32 + bb * 4];
            float4 p2 = *(const float4*)&S[1 * 4096 + tid2 * 32 + bb * 4];
            float4 p3 = *(const float4*)&S[2 * 4096 + tid2 * 32 + bb * 4];
            F2U pb; pb.u = accB[bb];
            float4 v;
            v.x = accA0[bb] + p1.x + (p2.x + p3.x) + bo0;
            v.y = accA1[bb] + p1.y + (p2.y + p3.y) + bo1;
            v.z = pb.f.x    + p1.z + (p2.z + p3.z) + bo2;
            v.w = pb.f.y    + p1.w + (p2.w + p3.w) + bo3;
            *(float4*)&out[(bRow + ty * 8 + bb) * OUT_DIM + oCol + tx * 4] = v;
        }
    }
}

extern "C" void kernel_launch(void* const* d_in, const int* in_sizes, int n_in,
                              void* d_out, int out_size) {
    const float* x      = (const float*)d_in[0];
    const float* weight = (const float*)d_in[1];
    const float* bias   = (const float*)d_in[2];
    float* out          = (float*)d_out;

    dim3 grid(OUT_DIM / BN, B_DIM / BM);  // (8, 16) = 128 CTAs
    trigo_kernel<<<grid, 512>>>(x, weight, bias, out);
}